// round 1
// baseline (speedup 1.0000x reference)
#include <cuda_runtime.h>
#include <math.h>

#define BTOT   65536
#define DIN    256
#define HDIM   64
#define ADIM   32
#define NACT   14
#define NS     8
#define BM     64
#define PT     65        // smem pitch (rows dim) -> conflict-free column reads
#define NTHREADS 256

// ---- persistent scratch for repacked weights (no allocation allowed) ----
__device__ __align__(16) float g_WihT[HDIM * 3 * HDIM];   // [k=64][j=192]
__device__ __align__(16) float g_WhhT[HDIM * 3 * HDIM];   // [k=64][j=192]
__device__ __align__(16) float g_qkvW[HDIM * 96];         // [k=64][q|k|v = 96]

__global__ void setup_kernel(const float* __restrict__ Wih,
                             const float* __restrict__ Whh,
                             const float* __restrict__ qW,
                             const float* __restrict__ kW,
                             const float* __restrict__ vW)
{
    const int stride = gridDim.x * blockDim.x;
    const int t0 = blockIdx.x * blockDim.x + threadIdx.x;
    for (int idx = t0; idx < HDIM * 192; idx += stride) {
        int k = idx / 192, j = idx - k * 192;
        g_WihT[idx] = Wih[j * HDIM + k];
        g_WhhT[idx] = Whh[j * HDIM + k];
    }
    for (int idx = t0; idx < HDIM * 96; idx += stride) {
        int k = idx / 96, a = idx - k * 96;
        float v;
        if (a < 32)      v = qW[k * 32 + a];
        else if (a < 64) v = kW[k * 32 + (a - 32)];
        else             v = vW[k * 32 + (a - 64)];
        g_qkvW[idx] = v;
    }
}

// One K=64 gate GEMM pair: ax = x @ WihT[:, g*64 + c0 .. +3], ah = h @ WhhT[...]
__device__ __forceinline__ void gate_gemm(const float* __restrict__ x_s,
                                          const float* __restrict__ h_s,
                                          int g, int r0, int c0,
                                          float ax[4][4], float ah[4][4])
{
#pragma unroll
    for (int i = 0; i < 4; i++)
#pragma unroll
        for (int j = 0; j < 4; j++) { ax[i][j] = 0.f; ah[i][j] = 0.f; }

#pragma unroll 4
    for (int k = 0; k < HDIM; k++) {
        const float4 wx = *reinterpret_cast<const float4*>(&g_WihT[k * 192 + g * 64 + c0]);
        const float4 wh = *reinterpret_cast<const float4*>(&g_WhhT[k * 192 + g * 64 + c0]);
        const float wxv[4] = {wx.x, wx.y, wx.z, wx.w};
        const float whv[4] = {wh.x, wh.y, wh.z, wh.w};
        const float* xp = &x_s[k * PT + r0];
        const float* hp = &h_s[k * PT + r0];
        float xv[4], hv[4];
#pragma unroll
        for (int i = 0; i < 4; i++) { xv[i] = xp[i]; hv[i] = hp[i]; }
#pragma unroll
        for (int i = 0; i < 4; i++)
#pragma unroll
            for (int j = 0; j < 4; j++) {
                ax[i][j] = fmaf(xv[i], wxv[j], ax[i][j]);
                ah[i][j] = fmaf(hv[i], whv[j], ah[i][j]);
            }
    }
}

__global__ void __launch_bounds__(NTHREADS, 2)
fused_kernel(const float* __restrict__ obs,
             const float* __restrict__ hid,
             const float* __restrict__ encW,
             const float* __restrict__ encb,
             const float* __restrict__ bih,
             const float* __restrict__ bhh,
             const float* __restrict__ vb,
             const float* __restrict__ decW,
             const float* __restrict__ decb,
             float* __restrict__ outp,
             float* __restrict__ houtp)
{
    extern __shared__ float sm[];
    float* A_s    = sm;                 // [64][PT]  obs k-tile (transposed)
    float* x_s    = sm + 4160;          // [64][PT]  encoder output (feat-major)
    float* h_s    = sm + 8320;          // [64][PT]  hidden_state (feat-major)
    float* ho_s   = sm + 12480;         // [64][PT]  h_out (feat-major)
    float* qkv_s  = sm;                 // [96][PT]  overlaps A_s + x_s (both dead)
    float* xatt_s = sm + 8320;          // [32][PT]  overlaps h_s (dead)

    const int tid  = threadIdx.x;
    const int trow = tid >> 4;
    const int tcol = tid & 15;
    const int r0 = trow * 4;
    const int c0 = tcol * 4;
    const int rowbase = blockIdx.x * BM;

    // load hidden_state tile transposed: h_s[j][r]
    for (int idx = tid; idx < BM * HDIM; idx += NTHREADS) {
        int r = idx >> 6, j = idx & 63;
        h_s[j * PT + r] = hid[(rowbase + r) * HDIM + j];
    }

    // ---------------- encoder: x = relu(obs @ enc_W + enc_b) ----------------
    float acc[4][4];
#pragma unroll
    for (int i = 0; i < 4; i++)
#pragma unroll
        for (int j = 0; j < 4; j++) acc[i][j] = 0.f;

    for (int kt = 0; kt < DIN / 64; kt++) {
        __syncthreads();
        for (int idx = tid; idx < BM * 64; idx += NTHREADS) {
            int r = idx >> 6, cc = idx & 63;
            A_s[cc * PT + r] = obs[(rowbase + r) * DIN + kt * 64 + cc];
        }
        __syncthreads();
#pragma unroll 8
        for (int kk = 0; kk < 64; kk++) {
            const float4 w = *reinterpret_cast<const float4*>(&encW[(kt * 64 + kk) * HDIM + c0]);
            const float wv[4] = {w.x, w.y, w.z, w.w};
            const float* ap = &A_s[kk * PT + r0];
            float av[4];
#pragma unroll
            for (int i = 0; i < 4; i++) av[i] = ap[i];
#pragma unroll
            for (int i = 0; i < 4; i++)
#pragma unroll
                for (int j = 0; j < 4; j++)
                    acc[i][j] = fmaf(av[i], wv[j], acc[i][j]);
        }
    }
    {
        float bv[4];
#pragma unroll
        for (int j = 0; j < 4; j++) bv[j] = encb[c0 + j];
#pragma unroll
        for (int i = 0; i < 4; i++)
#pragma unroll
            for (int j = 0; j < 4; j++)
                x_s[(c0 + j) * PT + r0 + i] = fmaxf(acc[i][j] + bv[j], 0.f);
    }
    __syncthreads();

    // ---------------- GRU cell (r, z in registers across passes) ------------
    float rg[4][4], zg[4][4];
    {
        float ax[4][4], ah[4][4];
        // r gate
        gate_gemm(x_s, h_s, 0, r0, c0, ax, ah);
        {
            float bx[4], bh[4];
#pragma unroll
            for (int j = 0; j < 4; j++) { bx[j] = bih[c0 + j]; bh[j] = bhh[c0 + j]; }
#pragma unroll
            for (int i = 0; i < 4; i++)
#pragma unroll
                for (int j = 0; j < 4; j++) {
                    float s = ax[i][j] + bx[j] + ah[i][j] + bh[j];
                    rg[i][j] = 1.f / (1.f + expf(-s));
                }
        }
        // z gate
        gate_gemm(x_s, h_s, 1, r0, c0, ax, ah);
        {
            float bx[4], bh[4];
#pragma unroll
            for (int j = 0; j < 4; j++) { bx[j] = bih[64 + c0 + j]; bh[j] = bhh[64 + c0 + j]; }
#pragma unroll
            for (int i = 0; i < 4; i++)
#pragma unroll
                for (int j = 0; j < 4; j++) {
                    float s = ax[i][j] + bx[j] + ah[i][j] + bh[j];
                    zg[i][j] = 1.f / (1.f + expf(-s));
                }
        }
        // n gate + h_out
        gate_gemm(x_s, h_s, 2, r0, c0, ax, ah);
        {
            float bx[4], bh[4];
#pragma unroll
            for (int j = 0; j < 4; j++) { bx[j] = bih[128 + c0 + j]; bh[j] = bhh[128 + c0 + j]; }
#pragma unroll
            for (int i = 0; i < 4; i++)
#pragma unroll
                for (int j = 0; j < 4; j++) {
                    float xn = ax[i][j] + bx[j];
                    float hn = ah[i][j] + bh[j];
                    float nn = tanhf(xn + rg[i][j] * hn);
                    float hp = h_s[(c0 + j) * PT + r0 + i];
                    ho_s[(c0 + j) * PT + r0 + i] = (1.f - zg[i][j]) * nn + zg[i][j] * hp;
                }
        }
    }
    __syncthreads();

    // ---------------- q|k|v = h_out @ [qW|kW|vW] (N=96) ---------------------
    {
        float qa[4][6];
#pragma unroll
        for (int i = 0; i < 4; i++)
#pragma unroll
            for (int m = 0; m < 6; m++) qa[i][m] = 0.f;
        const int cq = tcol * 6;
#pragma unroll 4
        for (int k = 0; k < HDIM; k++) {
            const float* ap = &ho_s[k * PT + r0];
            const float* wp = &g_qkvW[k * 96 + cq];
            float av[4];
#pragma unroll
            for (int i = 0; i < 4; i++) av[i] = ap[i];
#pragma unroll
            for (int m = 0; m < 6; m++) {
                float w = wp[m];
#pragma unroll
                for (int i = 0; i < 4; i++)
                    qa[i][m] = fmaf(av[i], w, qa[i][m]);
            }
        }
#pragma unroll
        for (int m = 0; m < 6; m++) {
            int cg = cq + m;
            bool isv = (cg >= 64);
            float bias = isv ? vb[cg - 64] : 0.f;
#pragma unroll
            for (int i = 0; i < 4; i++) {
                float v = qa[i][m] + bias;
                if (isv) v = fmaxf(v, 0.f);
                qkv_s[cg * PT + r0 + i] = v;
            }
        }
    }
    __syncthreads();

    // ---------------- exclude-self attention (8 groups of 8 rows) -----------
    if (tid < BM) {
        const int i = tid & 7;
        const int base = tid & ~7;       // group base row
        float q[ADIM];
#pragma unroll
        for (int a = 0; a < ADIM; a++) q[a] = qkv_s[a * PT + tid];
        float sc[NS];
        float mx = -1e30f;
#pragma unroll
        for (int j = 0; j < NS; j++) {
            float s = 0.f;
#pragma unroll
            for (int a = 0; a < ADIM; a++)
                s = fmaf(q[a], qkv_s[(32 + a) * PT + base + j], s);
            s *= 0.17677669529663689f;   // 1/sqrt(32)
            if (j == i) s = -1e9f;
            sc[j] = s;
            mx = fmaxf(mx, s);
        }
        float sum = 0.f;
#pragma unroll
        for (int j = 0; j < NS; j++) { sc[j] = expf(sc[j] - mx); sum += sc[j]; }
        const float inv = 1.f / sum;
#pragma unroll
        for (int a = 0; a < ADIM; a++) {
            float xa = 0.f;
#pragma unroll
            for (int j = 0; j < NS; j++)
                xa = fmaf(sc[j], qkv_s[(64 + a) * PT + base + j], xa);
            xatt_s[a * PT + tid] = xa * inv;
        }
    }
    __syncthreads();

    // ---------------- decoder: out = [h_out, xatt] @ decW + decb ------------
    for (int idx = tid; idx < BM * NACT; idx += NTHREADS) {
        int r = idx / NACT;
        int c = idx - r * NACT;
        float s = decb[c];
#pragma unroll 8
        for (int k = 0; k < HDIM; k++)
            s = fmaf(ho_s[k * PT + r], __ldg(&decW[k * NACT + c]), s);
#pragma unroll 8
        for (int k = 0; k < ADIM; k++)
            s = fmaf(xatt_s[k * PT + r], __ldg(&decW[(HDIM + k) * NACT + c]), s);
        outp[(rowbase + r) * NACT + c] = s;
    }

    // write h_out (coalesced)
    for (int idx = tid; idx < BM * HDIM; idx += NTHREADS) {
        int r = idx >> 6, j = idx & 63;
        houtp[(rowbase + r) * HDIM + j] = ho_s[j * PT + r];
    }
}

extern "C" void kernel_launch(void* const* d_in, const int* in_sizes, int n_in,
                              void* d_out, int out_size)
{
    (void)in_sizes; (void)n_in; (void)out_size;
    const float* obs  = (const float*)d_in[0];
    const float* hid  = (const float*)d_in[1];
    const float* encW = (const float*)d_in[2];
    const float* encb = (const float*)d_in[3];
    const float* Wih  = (const float*)d_in[4];
    const float* Whh  = (const float*)d_in[5];
    const float* bih  = (const float*)d_in[6];
    const float* bhh  = (const float*)d_in[7];
    const float* qW   = (const float*)d_in[8];
    const float* kW   = (const float*)d_in[9];
    const float* vW   = (const float*)d_in[10];
    const float* vb   = (const float*)d_in[11];
    const float* decW = (const float*)d_in[12];
    const float* decb = (const float*)d_in[13];

    float* outp  = (float*)d_out;                 // [B, 14]
    float* houtp = outp + (size_t)BTOT * NACT;    // [B, 64]

    setup_kernel<<<32, 256>>>(Wih, Whh, qW, kW, vW);

    const int smem_bytes = 16640 * sizeof(float); // 66,560 B
    cudaFuncSetAttribute(fused_kernel,
                         cudaFuncAttributeMaxDynamicSharedMemorySize, smem_bytes);
    fused_kernel<<<BTOT / BM, NTHREADS, smem_bytes>>>(
        obs, hid, encW, encb, bih, bhh, vb, decW, decb, outp, houtp);
}

// round 2
// speedup vs baseline: 1.3710x; 1.3710x over previous
#include <cuda_runtime.h>
#include <math.h>

#define BTOT   65536
#define DIN    256
#define HDIM   64
#define ADIM   32
#define NACT   14
#define NS     8
#define BM     64
#define PT     68        // pitch for 64-wide tiles (row-major), float4-aligned
#define PH     100       // pitch for ho_s rows: [0..63]=h_out, [64..95]=xatt
#define PQ     100       // pitch for qkv rows
#define PDW    100       // pitch for transposed decoder weights
#define NTHREADS 256

typedef unsigned long long ull;

// ---- persistent scratch for repacked weights (no allocation allowed) ----
__device__ __align__(16) float g_WihT[HDIM * 3 * HDIM];   // [k=64][j=192]
__device__ __align__(16) float g_WhhT[HDIM * 3 * HDIM];   // [k=64][j=192]
__device__ __align__(16) float g_qkvW[HDIM * 96];         // [k=64][q|k|v = 96]

__global__ void setup_kernel(const float* __restrict__ Wih,
                             const float* __restrict__ Whh,
                             const float* __restrict__ qW,
                             const float* __restrict__ kW,
                             const float* __restrict__ vW)
{
    const int stride = gridDim.x * blockDim.x;
    const int t0 = blockIdx.x * blockDim.x + threadIdx.x;
    for (int idx = t0; idx < HDIM * 192; idx += stride) {
        int k = idx / 192, j = idx - k * 192;
        g_WihT[idx] = Wih[j * HDIM + k];
        g_WhhT[idx] = Whh[j * HDIM + k];
    }
    for (int idx = t0; idx < HDIM * 96; idx += stride) {
        int k = idx / 96, a = idx - k * 96;
        float v;
        if (a < 32)      v = qW[k * 32 + a];
        else if (a < 64) v = kW[k * 32 + (a - 32)];
        else             v = vW[k * 32 + (a - 64)];
        g_qkvW[idx] = v;
    }
}

// ---------------- f32x2 helpers (Blackwell packed fp32) ----------------
__device__ __forceinline__ void ffma2(ull& acc, ull a, ull b) {
    asm("fma.rn.f32x2 %0, %1, %2, %0;" : "+l"(acc) : "l"(a), "l"(b));
}
__device__ __forceinline__ ull pack2(float x) {
    ull d; unsigned xi = __float_as_uint(x);
    asm("mov.b64 %0, {%1, %1};" : "=l"(d) : "r"(xi));
    return d;
}
__device__ __forceinline__ float2 unpack2(ull v) {
    float2 r;
    asm("mov.b64 {%0, %1}, %2;" : "=f"(r.x), "=f"(r.y) : "l"(v));
    return r;
}
__device__ __forceinline__ unsigned saddr(const void* p) {
    return (unsigned)__cvta_generic_to_shared(p);
}
__device__ __forceinline__ float sigmoidf_(float s) {
    return __fdividef(1.f, 1.f + __expf(-s));
}

// one GRU gate pair: ax = x @ WihT[:, g*64+c0..+3], ah = h @ WhhT[...]
__device__ __forceinline__ void gate_pass(const float* __restrict__ x_s,
                                          const float* __restrict__ h_s,
                                          int g, int r0, int c0,
                                          ull ax[4][2], ull ah[4][2])
{
#pragma unroll
    for (int i = 0; i < 4; i++) { ax[i][0] = 0; ax[i][1] = 0; ah[i][0] = 0; ah[i][1] = 0; }
#pragma unroll 4
    for (int k = 0; k < HDIM; k++) {
        const ulonglong2 wx = *reinterpret_cast<const ulonglong2*>(&g_WihT[k * 192 + g * 64 + c0]);
        const ulonglong2 wh = *reinterpret_cast<const ulonglong2*>(&g_WhhT[k * 192 + g * 64 + c0]);
        ull xd[4], hd[4];
#pragma unroll
        for (int i = 0; i < 4; i++) {
            xd[i] = pack2(x_s[(r0 + i) * PT + k]);
            hd[i] = pack2(h_s[(r0 + i) * PT + k]);
        }
#pragma unroll
        for (int i = 0; i < 4; i++) {
            ffma2(ax[i][0], xd[i], wx.x); ffma2(ax[i][1], xd[i], wx.y);
            ffma2(ah[i][0], hd[i], wh.x); ffma2(ah[i][1], hd[i], wh.y);
        }
    }
}

__global__ void __launch_bounds__(NTHREADS, 2)
fused_kernel(const float* __restrict__ obs,
             const float* __restrict__ hid,
             const float* __restrict__ encW,
             const float* __restrict__ encb,
             const float* __restrict__ bih,
             const float* __restrict__ bhh,
             const float* __restrict__ vb,
             const float* __restrict__ decW,
             const float* __restrict__ decb,
             float* __restrict__ outp,
             float* __restrict__ houtp)
{
    extern __shared__ float sm[];
    float* Abuf0 = sm;                 // [64][PT] obs tile (double buffer)
    float* Abuf1 = sm + 4352;
    float* x_s   = sm + 8704;          // [64][PT] encoder output
    float* h_s   = sm + 13056;         // [64][PT] hidden_state
    float* ho_s  = sm + 17408;         // [64][PH] h_out | xatt
    float* qkv_s = sm;                 // [64][PQ] overlays A buffers (dead)
    float* decWT = sm + 8704;          // [14][PDW] overlays x_s (dead)

    const int tid  = threadIdx.x;
    const int trow = tid >> 4;
    const int tcol = tid & 15;
    const int r0 = trow * 4;
    const int c0 = tcol * 4;
    const int rowbase = blockIdx.x * BM;

    // ---- prefetch obs tile 0 via cp.async ----
    {
        float* dst = Abuf0;
#pragma unroll
        for (int c = 0; c < 4; c++) {
            int chunk = tid + c * 256;               // 1024 chunks of 16B
            int row = chunk >> 4, off = (chunk & 15) * 4;
            const float* src = obs + (size_t)(rowbase + row) * DIN + off;
            unsigned d = saddr(&dst[row * PT + off]);
            asm volatile("cp.async.cg.shared.global [%0], [%1], 16;" :: "r"(d), "l"(src));
        }
        asm volatile("cp.async.commit_group;");
    }

    // ---- load hidden_state tile (row-major, float4) ----
    for (int v = tid; v < BM * 16; v += NTHREADS) {
        int r = v >> 4, cq = (v & 15) * 4;
        *reinterpret_cast<float4*>(&h_s[r * PT + cq]) =
            *reinterpret_cast<const float4*>(&hid[(size_t)(rowbase + r) * HDIM + cq]);
    }

    // ---------------- encoder: x = relu(obs @ enc_W + enc_b) ----------------
    ull eacc[4][2];
#pragma unroll
    for (int i = 0; i < 4; i++) { eacc[i][0] = 0; eacc[i][1] = 0; }

#pragma unroll
    for (int kt = 0; kt < 4; kt++) {
        __syncthreads();   // everyone done reading the buffer we're about to overwrite
        if (kt < 3) {
            float* dst = ((kt + 1) & 1) ? Abuf1 : Abuf0;
#pragma unroll
            for (int c = 0; c < 4; c++) {
                int chunk = tid + c * 256;
                int row = chunk >> 4, off = (chunk & 15) * 4;
                const float* src = obs + (size_t)(rowbase + row) * DIN + (kt + 1) * 64 + off;
                unsigned d = saddr(&dst[row * PT + off]);
                asm volatile("cp.async.cg.shared.global [%0], [%1], 16;" :: "r"(d), "l"(src));
            }
            asm volatile("cp.async.commit_group;");
            asm volatile("cp.async.wait_group 1;");
        } else {
            asm volatile("cp.async.wait_group 0;");
        }
        __syncthreads();

        const float* Ac = (kt & 1) ? Abuf1 : Abuf0;
#pragma unroll 4
        for (int k = 0; k < 64; k++) {
            const ulonglong2 w = *reinterpret_cast<const ulonglong2*>(&encW[(size_t)(kt * 64 + k) * HDIM + c0]);
            ull xd[4];
#pragma unroll
            for (int i = 0; i < 4; i++) xd[i] = pack2(Ac[(r0 + i) * PT + k]);
#pragma unroll
            for (int i = 0; i < 4; i++) { ffma2(eacc[i][0], xd[i], w.x); ffma2(eacc[i][1], xd[i], w.y); }
        }
    }
    {
        const float4 b4 = *reinterpret_cast<const float4*>(&encb[c0]);
#pragma unroll
        for (int i = 0; i < 4; i++) {
            float2 p0 = unpack2(eacc[i][0]), p1 = unpack2(eacc[i][1]);
            float4 o;
            o.x = fmaxf(p0.x + b4.x, 0.f); o.y = fmaxf(p0.y + b4.y, 0.f);
            o.z = fmaxf(p1.x + b4.z, 0.f); o.w = fmaxf(p1.y + b4.w, 0.f);
            *reinterpret_cast<float4*>(&x_s[(r0 + i) * PT + c0]) = o;
        }
    }
    __syncthreads();

    // ---------------- GRU cell (r, z kept in registers) ----------------
    {
        float rg[4][4], zg[4][4];
        ull ax[4][2], ah[4][2];

        gate_pass(x_s, h_s, 0, r0, c0, ax, ah);
        {
            const float4 bx = *reinterpret_cast<const float4*>(&bih[c0]);
            const float4 bh = *reinterpret_cast<const float4*>(&bhh[c0]);
            const float bxv[4] = {bx.x, bx.y, bx.z, bx.w}, bhv[4] = {bh.x, bh.y, bh.z, bh.w};
#pragma unroll
            for (int i = 0; i < 4; i++) {
                float2 px0 = unpack2(ax[i][0]), px1 = unpack2(ax[i][1]);
                float2 ph0 = unpack2(ah[i][0]), ph1 = unpack2(ah[i][1]);
                rg[i][0] = sigmoidf_(px0.x + bxv[0] + ph0.x + bhv[0]);
                rg[i][1] = sigmoidf_(px0.y + bxv[1] + ph0.y + bhv[1]);
                rg[i][2] = sigmoidf_(px1.x + bxv[2] + ph1.x + bhv[2]);
                rg[i][3] = sigmoidf_(px1.y + bxv[3] + ph1.y + bhv[3]);
            }
        }
        gate_pass(x_s, h_s, 1, r0, c0, ax, ah);
        {
            const float4 bx = *reinterpret_cast<const float4*>(&bih[64 + c0]);
            const float4 bh = *reinterpret_cast<const float4*>(&bhh[64 + c0]);
            const float bxv[4] = {bx.x, bx.y, bx.z, bx.w}, bhv[4] = {bh.x, bh.y, bh.z, bh.w};
#pragma unroll
            for (int i = 0; i < 4; i++) {
                float2 px0 = unpack2(ax[i][0]), px1 = unpack2(ax[i][1]);
                float2 ph0 = unpack2(ah[i][0]), ph1 = unpack2(ah[i][1]);
                zg[i][0] = sigmoidf_(px0.x + bxv[0] + ph0.x + bhv[0]);
                zg[i][1] = sigmoidf_(px0.y + bxv[1] + ph0.y + bhv[1]);
                zg[i][2] = sigmoidf_(px1.x + bxv[2] + ph1.x + bhv[2]);
                zg[i][3] = sigmoidf_(px1.y + bxv[3] + ph1.y + bhv[3]);
            }
        }
        gate_pass(x_s, h_s, 2, r0, c0, ax, ah);
        {
            const float4 bx = *reinterpret_cast<const float4*>(&bih[128 + c0]);
            const float4 bh = *reinterpret_cast<const float4*>(&bhh[128 + c0]);
            const float bxv[4] = {bx.x, bx.y, bx.z, bx.w}, bhv[4] = {bh.x, bh.y, bh.z, bh.w};
#pragma unroll
            for (int i = 0; i < 4; i++) {
                float2 px0 = unpack2(ax[i][0]), px1 = unpack2(ax[i][1]);
                float2 ph0 = unpack2(ah[i][0]), ph1 = unpack2(ah[i][1]);
                float xn[4] = {px0.x + bxv[0], px0.y + bxv[1], px1.x + bxv[2], px1.y + bxv[3]};
                float hn[4] = {ph0.x + bhv[0], ph0.y + bhv[1], ph1.x + bhv[2], ph1.y + bhv[3]};
                float4 o;
                float* op = &o.x;
#pragma unroll
                for (int j = 0; j < 4; j++) {
                    float nn = tanhf(xn[j] + rg[i][j] * hn[j]);
                    float hp = h_s[(r0 + i) * PT + c0 + j];
                    op[j] = (1.f - zg[i][j]) * nn + zg[i][j] * hp;
                }
                *reinterpret_cast<float4*>(&ho_s[(r0 + i) * PH + c0]) = o;
            }
        }
    }
    __syncthreads();

    // ---------------- q|k|v = h_out @ [qW|kW|vW]  (N=96, tile 4x6) ----------
    {
        const int cq = tcol * 6;
        ull qa[4][3];
#pragma unroll
        for (int i = 0; i < 4; i++) { qa[i][0] = 0; qa[i][1] = 0; qa[i][2] = 0; }
#pragma unroll 4
        for (int k = 0; k < HDIM; k++) {
            const ull* wp = reinterpret_cast<const ull*>(&g_qkvW[k * 96 + cq]);
            ull w0 = wp[0], w1 = wp[1], w2 = wp[2];
#pragma unroll
            for (int i = 0; i < 4; i++) {
                ull hv = pack2(ho_s[(r0 + i) * PH + k]);
                ffma2(qa[i][0], hv, w0); ffma2(qa[i][1], hv, w1); ffma2(qa[i][2], hv, w2);
            }
        }
#pragma unroll
        for (int i = 0; i < 4; i++) {
#pragma unroll
            for (int m = 0; m < 3; m++) {
                float2 p = unpack2(qa[i][m]);
                float pv[2] = {p.x, p.y};
#pragma unroll
                for (int l = 0; l < 2; l++) {
                    int cg = cq + 2 * m + l;
                    float v = pv[l];
                    if (cg >= 64) v = fmaxf(v + vb[cg - 64], 0.f);
                    qkv_s[(r0 + i) * PQ + cg] = v;
                }
            }
        }
        // h_out writeback (coalesced float4) — independent of attention
        for (int v = tid; v < BM * 16; v += NTHREADS) {
            int r = v >> 4, cc = (v & 15) * 4;
            *reinterpret_cast<float4*>(&houtp[(size_t)(rowbase + r) * HDIM + cc]) =
                *reinterpret_cast<const float4*>(&ho_s[r * PH + cc]);
        }
    }
    __syncthreads();

    // ---------------- exclude-self attention + decW transpose ---------------
    if (tid < BM) {
        const int ii = tid & 7;
        const int base = tid & ~7;
        float q[ADIM];
#pragma unroll
        for (int a4 = 0; a4 < 8; a4++) {
            float4 t = *reinterpret_cast<const float4*>(&qkv_s[tid * PQ + a4 * 4]);
            q[a4 * 4 + 0] = t.x; q[a4 * 4 + 1] = t.y; q[a4 * 4 + 2] = t.z; q[a4 * 4 + 3] = t.w;
        }
        float sc[NS]; float mx = -1e30f;
#pragma unroll
        for (int j = 0; j < NS; j++) {
            float s = 0.f;
#pragma unroll
            for (int a4 = 0; a4 < 8; a4++) {
                float4 t = *reinterpret_cast<const float4*>(&qkv_s[(base + j) * PQ + 32 + a4 * 4]);
                s = fmaf(q[a4 * 4 + 0], t.x, s); s = fmaf(q[a4 * 4 + 1], t.y, s);
                s = fmaf(q[a4 * 4 + 2], t.z, s); s = fmaf(q[a4 * 4 + 3], t.w, s);
            }
            s *= 0.17677669529663689f;
            if (j == ii) s = -1e9f;
            sc[j] = s; mx = fmaxf(mx, s);
        }
        float sum = 0.f;
#pragma unroll
        for (int j = 0; j < NS; j++) { sc[j] = __expf(sc[j] - mx); sum += sc[j]; }
        const float inv = __fdividef(1.f, sum);
        float xa[ADIM];
#pragma unroll
        for (int a = 0; a < ADIM; a++) xa[a] = 0.f;
#pragma unroll
        for (int j = 0; j < NS; j++) {
            float w = sc[j] * inv;
#pragma unroll
            for (int a4 = 0; a4 < 8; a4++) {
                float4 t = *reinterpret_cast<const float4*>(&qkv_s[(base + j) * PQ + 64 + a4 * 4]);
                xa[a4 * 4 + 0] = fmaf(w, t.x, xa[a4 * 4 + 0]);
                xa[a4 * 4 + 1] = fmaf(w, t.y, xa[a4 * 4 + 1]);
                xa[a4 * 4 + 2] = fmaf(w, t.z, xa[a4 * 4 + 2]);
                xa[a4 * 4 + 3] = fmaf(w, t.w, xa[a4 * 4 + 3]);
            }
        }
#pragma unroll
        for (int a4 = 0; a4 < 8; a4++) {
            float4 o = make_float4(xa[a4 * 4], xa[a4 * 4 + 1], xa[a4 * 4 + 2], xa[a4 * 4 + 3]);
            *reinterpret_cast<float4*>(&ho_s[tid * PH + 64 + a4 * 4]) = o;
        }
    } else {
        // idle threads transpose decW into smem: decWT[c][k] (pitch PDW)
        for (int v = tid - 64; v < NACT * 96; v += NTHREADS - 64) {
            int c = v / 96, k = v - c * 96;
            decWT[c * PDW + k] = decW[k * NACT + c];
        }
    }
    __syncthreads();

    // ---------------- decoder: out = [h_out|xatt] @ decW + decb -------------
    for (int idx = tid; idx < BM * NACT; idx += NTHREADS) {
        int r = idx / NACT;
        int c = idx - r * NACT;
        const ull* hp = reinterpret_cast<const ull*>(&ho_s[r * PH]);
        const ull* wp = reinterpret_cast<const ull*>(&decWT[c * PDW]);
        ull acc = 0;
#pragma unroll 8
        for (int kp = 0; kp < 48; kp++) ffma2(acc, hp[kp], wp[kp]);
        float2 p = unpack2(acc);
        outp[(size_t)(rowbase + r) * NACT + c] = p.x + p.y + decb[c];
    }
}

extern "C" void kernel_launch(void* const* d_in, const int* in_sizes, int n_in,
                              void* d_out, int out_size)
{
    (void)in_sizes; (void)n_in; (void)out_size;
    const float* obs  = (const float*)d_in[0];
    const float* hid  = (const float*)d_in[1];
    const float* encW = (const float*)d_in[2];
    const float* encb = (const float*)d_in[3];
    const float* Wih  = (const float*)d_in[4];
    const float* Whh  = (const float*)d_in[5];
    const float* bih  = (const float*)d_in[6];
    const float* bhh  = (const float*)d_in[7];
    const float* qW   = (const float*)d_in[8];
    const float* kW   = (const float*)d_in[9];
    const float* vW   = (const float*)d_in[10];
    const float* vb   = (const float*)d_in[11];
    const float* decW = (const float*)d_in[12];
    const float* decb = (const float*)d_in[13];

    float* outp  = (float*)d_out;                 // [B, 14]
    float* houtp = outp + (size_t)BTOT * NACT;    // [B, 64]

    setup_kernel<<<32, 256>>>(Wih, Whh, qW, kW, vW);

    const int smem_bytes = 23808 * sizeof(float); // 95,232 B
    cudaFuncSetAttribute(fused_kernel,
                         cudaFuncAttributeMaxDynamicSharedMemorySize, smem_bytes);
    fused_kernel<<<BTOT / BM, NTHREADS, smem_bytes>>>(
        obs, hid, encW, encb, bih, bhh, vb, decW, decb, outp, houtp);
}